// round 2
// baseline (speedup 1.0000x reference)
#include <cuda_runtime.h>
#include <math.h>

#define DD 64
#define NMAX 50000
#define EMAX 800000
#define INV_SQRT2 0.70710678118654752440f

// ---- scratch (device globals: allocation-free) ----
__device__ float g_emb[(size_t)EMAX * DD];   // bond-encoder output, permuted into dst order
__device__ float g_agg[(size_t)NMAX * DD];   // (1+eps)x + aggregated messages
__device__ float g_h[(size_t)NMAX * DD];     // MLP output (pre-BN)
__device__ float g_xa[(size_t)NMAX * DD];    // x ping
__device__ float g_xb[(size_t)NMAX * DD];    // x pong
__device__ float g_bsum[DD];                 // BN sum per feature
__device__ float g_bsq[DD];                  // BN sumsq per feature
// sort scratch
__device__ int g_off[NMAX + 1];              // CSR offsets by dst
__device__ int g_cur[NMAX];                  // counts / cursors
__device__ int g_srcs[EMAX];                 // src id, permuted into dst order
__device__ int g_pos[EMAX];                  // sorted position of original edge e

__device__ __forceinline__ float gelu_exact(float v) {
    return v * normcdff(v);   // jax.nn.gelu(approximate=False)
}
__device__ __forceinline__ float4 gelu4(float4 v) {
    v.x = gelu_exact(v.x); v.y = gelu_exact(v.y);
    v.z = gelu_exact(v.z); v.w = gelu_exact(v.w);
    return v;
}

__device__ __forceinline__ const float* sel_in(int s, const float* ext) {
    return (s == 0) ? ext : ((s == 1) ? g_xa : g_xb);
}
__device__ __forceinline__ float* sel_out(int s, float* ext) {
    return (s == 0) ? ext : ((s == 1) ? g_xa : g_xb);
}

// ============================================================
// Sort phase: counting sort of edges by dst
// ============================================================
__global__ void k_cnt0(int N)
{
    int i = blockIdx.x * blockDim.x + threadIdx.x;
    if (i < N) g_cur[i] = 0;
}

__global__ void k_count(const int* __restrict__ dst, int E)
{
    int e = blockIdx.x * blockDim.x + threadIdx.x;
    if (e < E) atomicAdd(&g_cur[dst[e]], 1);
}

// single block, 1024 threads: exclusive scan of counts -> g_off, reset g_cur
__global__ void __launch_bounds__(1024) k_scan(int N, int E)
{
    __shared__ int ssum[1024];
    int t = threadIdx.x;
    int C = (N + 1023) >> 10;
    int beg = t * C;
    int end = min(beg + C, N);
    int s = 0;
    for (int i = beg; i < end; i++) s += g_cur[i];
    ssum[t] = s;
    __syncthreads();
    for (int off = 1; off < 1024; off <<= 1) {
        int v = (t >= off) ? ssum[t - off] : 0;
        __syncthreads();
        ssum[t] += v;
        __syncthreads();
    }
    int run = (t == 0) ? 0 : ssum[t - 1];
    for (int i = beg; i < end; i++) {
        int c = g_cur[i];
        g_off[i] = run;
        run += c;
        g_cur[i] = 0;
    }
    if (beg < N && end == N) g_off[N] = run;
}

__global__ void k_scatter(const int* __restrict__ src,
                          const int* __restrict__ dst, int E)
{
    int e = blockIdx.x * blockDim.x + threadIdx.x;
    if (e >= E) return;
    int t = dst[e];
    int r = atomicAdd(&g_cur[t], 1);
    int p = g_off[t] + r;
    g_pos[e]  = p;
    g_srcs[p] = src[e];
}

// ============================================================
// K0: edge_emb = edge_attr @ W_be + b_be, written in dst-sorted order.
// 2 warps per edge row (thread owns output dim d); 4 rows per iteration
// for 4 independent FMA chains (latency hiding).
// ============================================================
__global__ void k_bond(const float* __restrict__ attr,
                       const float* __restrict__ Wbe,
                       const float* __restrict__ bbe, int E)
{
    int gw   = (blockIdx.x * blockDim.x + threadIdx.x) >> 5;
    int lane = threadIdx.x & 31;
    int nw   = (gridDim.x * blockDim.x) >> 5;
    int d    = (gw & 1) * 32 + lane;

    float w[DD];
#pragma unroll
    for (int k = 0; k < DD; k++) w[k] = Wbe[k * DD + d];
    float bias = bbe[d];

    int base   = (gw >> 1) * 4;
    int stride = (nw >> 1) * 4;

    for (int row = base; row < E; row += stride) {
        bool f1 = (row + 1) < E, f2 = (row + 2) < E, f3 = (row + 3) < E;
        const float4* a0 = (const float4*)(attr + (size_t)row * DD);
        const float4* a1 = (const float4*)(attr + (size_t)(row + (f1 ? 1 : 0)) * DD);
        const float4* a2 = (const float4*)(attr + (size_t)(row + (f2 ? 2 : 0)) * DD);
        const float4* a3 = (const float4*)(attr + (size_t)(row + (f3 ? 3 : 0)) * DD);
        float acc0 = bias, acc1 = bias, acc2 = bias, acc3 = bias;
#pragma unroll
        for (int k4 = 0; k4 < 16; k4++) {
            float4 v0 = a0[k4], v1 = a1[k4], v2 = a2[k4], v3 = a3[k4];
            acc0 = fmaf(v0.x, w[4*k4+0], acc0); acc0 = fmaf(v0.y, w[4*k4+1], acc0);
            acc0 = fmaf(v0.z, w[4*k4+2], acc0); acc0 = fmaf(v0.w, w[4*k4+3], acc0);
            acc1 = fmaf(v1.x, w[4*k4+0], acc1); acc1 = fmaf(v1.y, w[4*k4+1], acc1);
            acc1 = fmaf(v1.z, w[4*k4+2], acc1); acc1 = fmaf(v1.w, w[4*k4+3], acc1);
            acc2 = fmaf(v2.x, w[4*k4+0], acc2); acc2 = fmaf(v2.y, w[4*k4+1], acc2);
            acc2 = fmaf(v2.z, w[4*k4+2], acc2); acc2 = fmaf(v2.w, w[4*k4+3], acc2);
            acc3 = fmaf(v3.x, w[4*k4+0], acc3); acc3 = fmaf(v3.y, w[4*k4+1], acc3);
            acc3 = fmaf(v3.z, w[4*k4+2], acc3); acc3 = fmaf(v3.w, w[4*k4+3], acc3);
        }
        g_emb[(size_t)g_pos[row] * DD + d] = acc0;
        if (f1) g_emb[(size_t)g_pos[row+1] * DD + d] = acc1;
        if (f2) g_emb[(size_t)g_pos[row+2] * DD + d] = acc2;
        if (f3) g_emb[(size_t)g_pos[row+3] * DD + d] = acc3;
    }
}

// ============================================================
// K_agg: per-node gather-reduce (no atomics).
// 16 threads per node (thread q owns float4 q of the row).
// Output: g_agg[n] = (1+eps)*x[n] + sum_{edges->n} gelu(x[src]+emb)
// Also zeroes BN stats (block 0).
// ============================================================
__global__ void __launch_bounds__(256) k_agg(
    int xsel, const float* __restrict__ xext,
    const float* __restrict__ epsp, int layer, int N)
{
    if (blockIdx.x == 0 && threadIdx.x < DD) {
        g_bsum[threadIdx.x] = 0.f;
        g_bsq[threadIdx.x]  = 0.f;
    }
    int g = threadIdx.x >> 4;          // group 0..15 within block
    int q = threadIdx.x & 15;          // float4 index within row
    int n = blockIdx.x * 16 + g;
    if (n >= N) return;

    const float4* x4   = (const float4*)sel_in(xsel, xext);
    const float4* emb4 = (const float4*)g_emb;

    int beg = g_off[n], end = g_off[n + 1];
    float4 acc = make_float4(0.f, 0.f, 0.f, 0.f);
    for (int r = beg; r < end; r++) {
        int s = __ldg(&g_srcs[r]);
        float4 v  = emb4[(size_t)r * 16 + q];
        float4 xs = x4[(size_t)s * 16 + q];
        v.x += xs.x; v.y += xs.y; v.z += xs.z; v.w += xs.w;
        v = gelu4(v);
        acc.x += v.x; acc.y += v.y; acc.z += v.z; acc.w += v.w;
    }
    float eps1 = 1.0f + epsp[layer];
    float4 xv = x4[(size_t)n * 16 + q];
    acc.x = fmaf(eps1, xv.x, acc.x);
    acc.y = fmaf(eps1, xv.y, acc.y);
    acc.z = fmaf(eps1, xv.z, acc.z);
    acc.w = fmaf(eps1, xv.w, acc.w);
    ((float4*)g_agg)[(size_t)n * 16 + q] = acc;
}

// ============================================================
// K_mlp: h = gelu(agg @ W1 + b1) @ W2 + b2 ; accumulate BN stats.
// 64 threads/block (thread owns output dim d), 4 rows per iteration.
// ============================================================
__global__ void __launch_bounds__(64) k_mlp(
    const float* __restrict__ W1, const float* __restrict__ b1,
    const float* __restrict__ W2, const float* __restrict__ b2, int N)
{
    __shared__ float4 s_in4[4][16];
    __shared__ float4 s_h14[4][16];
    float* s_in = (float*)s_in4;
    float* s_h1 = (float*)s_h14;

    int d = threadIdx.x;

    float w1[DD], w2[DD];
#pragma unroll
    for (int k = 0; k < DD; k++) w1[k] = W1[k * DD + d];
#pragma unroll
    for (int k = 0; k < DD; k++) w2[k] = W2[k * DD + d];
    float bb1 = b1[d], bb2 = b2[d];

    float lsum = 0.f, lsq = 0.f;

    for (int base = blockIdx.x * 4; base < N; base += gridDim.x * 4) {
        int nr = min(4, N - base);
#pragma unroll
        for (int r = 0; r < 4; r++)
            if (r < nr) s_in[r * DD + d] = g_agg[(size_t)(base + r) * DD + d];
        __syncthreads();

        float a0 = bb1, a1 = bb1, a2 = bb1, a3 = bb1;
#pragma unroll
        for (int k4 = 0; k4 < 16; k4++) {
            float4 v0 = s_in4[0][k4], v1 = s_in4[1][k4], v2 = s_in4[2][k4], v3 = s_in4[3][k4];
            a0 = fmaf(v0.x, w1[4*k4+0], a0); a0 = fmaf(v0.y, w1[4*k4+1], a0);
            a0 = fmaf(v0.z, w1[4*k4+2], a0); a0 = fmaf(v0.w, w1[4*k4+3], a0);
            a1 = fmaf(v1.x, w1[4*k4+0], a1); a1 = fmaf(v1.y, w1[4*k4+1], a1);
            a1 = fmaf(v1.z, w1[4*k4+2], a1); a1 = fmaf(v1.w, w1[4*k4+3], a1);
            a2 = fmaf(v2.x, w1[4*k4+0], a2); a2 = fmaf(v2.y, w1[4*k4+1], a2);
            a2 = fmaf(v2.z, w1[4*k4+2], a2); a2 = fmaf(v2.w, w1[4*k4+3], a2);
            a3 = fmaf(v3.x, w1[4*k4+0], a3); a3 = fmaf(v3.y, w1[4*k4+1], a3);
            a3 = fmaf(v3.z, w1[4*k4+2], a3); a3 = fmaf(v3.w, w1[4*k4+3], a3);
        }
        s_h1[0 * DD + d] = gelu_exact(a0);
        s_h1[1 * DD + d] = gelu_exact(a1);
        s_h1[2 * DD + d] = gelu_exact(a2);
        s_h1[3 * DD + d] = gelu_exact(a3);
        __syncthreads();

        float c0 = bb2, c1 = bb2, c2 = bb2, c3 = bb2;
#pragma unroll
        for (int k4 = 0; k4 < 16; k4++) {
            float4 v0 = s_h14[0][k4], v1 = s_h14[1][k4], v2 = s_h14[2][k4], v3 = s_h14[3][k4];
            c0 = fmaf(v0.x, w2[4*k4+0], c0); c0 = fmaf(v0.y, w2[4*k4+1], c0);
            c0 = fmaf(v0.z, w2[4*k4+2], c0); c0 = fmaf(v0.w, w2[4*k4+3], c0);
            c1 = fmaf(v1.x, w2[4*k4+0], c1); c1 = fmaf(v1.y, w2[4*k4+1], c1);
            c1 = fmaf(v1.z, w2[4*k4+2], c1); c1 = fmaf(v1.w, w2[4*k4+3], c1);
            c2 = fmaf(v2.x, w2[4*k4+0], c2); c2 = fmaf(v2.y, w2[4*k4+1], c2);
            c2 = fmaf(v2.z, w2[4*k4+2], c2); c2 = fmaf(v2.w, w2[4*k4+3], c2);
            c3 = fmaf(v3.x, w2[4*k4+0], c3); c3 = fmaf(v3.y, w2[4*k4+1], c3);
            c3 = fmaf(v3.z, w2[4*k4+2], c3); c3 = fmaf(v3.w, w2[4*k4+3], c3);
        }
        float cc[4] = {c0, c1, c2, c3};
#pragma unroll
        for (int r = 0; r < 4; r++) {
            if (r < nr) {
                g_h[(size_t)(base + r) * DD + d] = cc[r];
                lsum += cc[r];
                lsq = fmaf(cc[r], cc[r], lsq);
            }
        }
        __syncthreads();
    }
    atomicAdd(&g_bsum[d], lsum);
    atomicAdd(&g_bsq[d],  lsq);
}

// ============================================================
// K_bn: x_next = (x + gelu(BN(h))) * INV_SQRT2
// ============================================================
__global__ void k_bn(int xsel, const float* __restrict__ xext,
                     int osel, float* __restrict__ oext,
                     const float* __restrict__ gamma,
                     const float* __restrict__ beta, int N)
{
    int idx = blockIdx.x * blockDim.x + threadIdx.x;
    int tot = N * 16;
    if (idx >= tot) return;
    const float* xin = sel_in(xsel, xext);
    float* xout = sel_out(osel, oext);

    int q = idx & 15;
    float invN = 1.0f / (float)N;
    float4 hv = ((const float4*)g_h)[idx];
    float4 xv = ((const float4*)xin)[idx];
    float hvv[4] = {hv.x, hv.y, hv.z, hv.w};
    float xvv[4] = {xv.x, xv.y, xv.z, xv.w};
    float o[4];
#pragma unroll
    for (int j = 0; j < 4; j++) {
        int dd = q * 4 + j;
        float mu   = g_bsum[dd] * invN;
        float var  = g_bsq[dd] * invN - mu * mu;
        float rstd = rsqrtf(var + 1e-5f);
        float hn   = (hvv[j] - mu) * rstd * gamma[dd] + beta[dd];
        o[j] = (xvv[j] + gelu_exact(hn)) * INV_SQRT2;
    }
    ((float4*)xout)[idx] = make_float4(o[0], o[1], o[2], o[3]);
}

// ============================================================
// launcher
// ============================================================
extern "C" void kernel_launch(void* const* d_in, const int* in_sizes, int n_in,
                              void* d_out, int out_size)
{
    const float* x0    = (const float*)d_in[0];
    const int*   eidx  = (const int*)  d_in[1];
    const float* eattr = (const float*)d_in[2];
    const float* Wbe   = (const float*)d_in[3];
    const float* bbe   = (const float*)d_in[4];
    const float* epsp  = (const float*)d_in[5];
    const float* W1    = (const float*)d_in[6];
    const float* b1    = (const float*)d_in[7];
    const float* W2    = (const float*)d_in[8];
    const float* b2    = (const float*)d_in[9];
    const float* gamma = (const float*)d_in[10];
    const float* beta  = (const float*)d_in[11];

    int N = in_sizes[0] / DD;
    int E = in_sizes[1] / 2;
    const int* src = eidx;
    const int* dst = eidx + E;

    // ---- one-time sort of edges by dst (counting sort) ----
    k_cnt0   <<<(N + 255) / 256, 256>>>(N);
    k_count  <<<(E + 255) / 256, 256>>>(dst, E);
    k_scan   <<<1, 1024>>>(N, E);
    k_scatter<<<(E + 255) / 256, 256>>>(src, dst, E);

    // ---- bond encoder once, written in sorted order ----
    k_bond<<<592, 256>>>(eattr, Wbe, bbe, E);

    // x schedule: L0: ext(x0)->g_xa ; L1: g_xa->g_xb ; L2: g_xb->ext(d_out)
    int in_sel[3]  = {0, 1, 2};
    int out_sel[3] = {1, 2, 0};

    int nblk_node16 = (N + 15) / 16;
    int nblk_node   = (N * 16 + 255) / 256;

    for (int l = 0; l < 3; l++) {
        const float* xext = (l == 0) ? x0 : nullptr;
        k_agg<<<nblk_node16, 256>>>(in_sel[l], xext, epsp, l, N);
        k_mlp<<<2048, 64>>>(W1 + (size_t)l * DD * DD, b1 + (size_t)l * DD,
                            W2 + (size_t)l * DD * DD, b2 + (size_t)l * DD, N);
        k_bn <<<nblk_node, 256>>>(in_sel[l], xext, out_sel[l], (float*)d_out,
                                  gamma + (size_t)l * DD, beta + (size_t)l * DD, N);
    }
}